// round 11
// baseline (speedup 1.0000x reference)
#include <cuda_runtime.h>
#include <cuda_bf16.h>
#include <cstdint>
#include <math.h>

// Problem constants
#define NB    16
#define LQ    300
#define CC    256
#define NHEAD 8
#define NLVL  3
#define NPT   4
#define LV    8400
#define HD    32

// Scratch
__device__ float g_v[(size_t)NB * LV * CC];        // projected value (~137.6 MB)
__device__ float g_wt[(size_t)CC * CC];            // W_val^T (tf32-rounded)
__device__ float g_wq[(size_t)CC * 288];           // [W_off | W_attn]
__device__ float g_bq[288];
__device__ float g_q[(size_t)NB * LQ * 288];       // fused off+attn logits
__device__ float g_samp[(size_t)NB * LQ * CC];

__device__ __forceinline__ float tf32_rna(float x) {
    uint32_t r;
    asm("cvt.rna.tf32.f32 %0, %1;" : "=r"(r) : "f"(x));
    return __uint_as_float(r);
}
__device__ __forceinline__ uint32_t smem_u32(const void* p) {
    uint32_t a;
    asm("{ .reg .u64 t; cvta.to.shared.u64 t, %1; cvt.u32.u64 %0, t; }" : "=r"(a) : "l"(p));
    return a;
}
__device__ __forceinline__ void cp16(uint32_t dst, const void* src) {
    asm volatile("cp.async.cg.shared.global [%0], [%1], 16;" :: "r"(dst), "l"(src));
}
__device__ __forceinline__ void cp_commit() { asm volatile("cp.async.commit_group;"); }
__device__ __forceinline__ void cp_wait1()  { asm volatile("cp.async.wait_group 1;"); }
__device__ __forceinline__ void cp_wait0()  { asm volatile("cp.async.wait_group 0;"); }

__device__ __forceinline__ void mma_tf32_16x8x8(
    float& d0, float& d1, float& d2, float& d3,
    uint32_t a0, uint32_t a1, uint32_t a2, uint32_t a3,
    uint32_t b0, uint32_t b1)
{
    asm volatile(
        "mma.sync.aligned.m16n8k8.row.col.f32.tf32.tf32.f32 "
        "{%0,%1,%2,%3}, {%4,%5,%6,%7}, {%8,%9}, {%0,%1,%2,%3};"
        : "+f"(d0), "+f"(d1), "+f"(d2), "+f"(d3)
        : "r"(a0), "r"(a1), "r"(a2), "r"(a3), "r"(b0), "r"(b1));
}

// ===========================================================================
// Prep kernels
// ===========================================================================
__global__ void transpose256_kernel(const float* __restrict__ W, float* __restrict__ WT) {
    __shared__ float t[32][33];
    int x = blockIdx.x * 32 + threadIdx.x;
    int y = blockIdx.y * 32 + threadIdx.y;
    #pragma unroll
    for (int j = 0; j < 32; j += 8)
        t[threadIdx.y + j][threadIdx.x] = W[(y + j) * 256 + x];
    __syncthreads();
    x = blockIdx.y * 32 + threadIdx.x;
    y = blockIdx.x * 32 + threadIdx.y;
    #pragma unroll
    for (int j = 0; j < 32; j += 8)
        WT[(y + j) * 256 + x] = tf32_rna(t[threadIdx.x][threadIdx.y + j]);
}

__global__ void prep_qcat_kernel(
    const float* __restrict__ W_off, const float* __restrict__ b_off,
    const float* __restrict__ W_attn, const float* __restrict__ b_attn,
    float* __restrict__ Wq, float* __restrict__ bq)
{
    int idx = blockIdx.x * 256 + threadIdx.x;
    if (idx < 256 * 288) {
        int r = idx / 288, c = idx % 288;
        Wq[idx] = (c < 192) ? W_off[r * 192 + c] : W_attn[r * 96 + (c - 192)];
    }
    if (idx < 288) bq[idx] = (idx < 192) ? b_off[idx] : b_attn[idx - 192];
}

// ===========================================================================
// SIMT GEMM tile (device fn): C[m0:+64, n0:+128] = A@B + bias
// 256 threads, TM=4, TN=8, BK=16. Uses caller-provided smem (>=3264 floats).
// ===========================================================================
__device__ __forceinline__ void simt_gemm_tile(
    float* sm, const float* __restrict__ A, const float* __restrict__ B,
    const float* __restrict__ bias, float* __restrict__ C,
    int N, int K, int m0, int n0)
{
    float (*As)[68]  = (float(*)[68])sm;              // 16 x 68
    float (*Bs)[132] = (float(*)[132])(sm + 16 * 68); // 16 x 132

    const int tid = threadIdx.x;
    const int tx = tid & 15;
    const int ty = tid >> 4;

    float acc[4][8];
    #pragma unroll
    for (int i = 0; i < 4; i++)
        #pragma unroll
        for (int j = 0; j < 8; j++) acc[i][j] = 0.f;

    for (int k0 = 0; k0 < K; k0 += 16) {
        {
            int r = tid >> 2, c4 = (tid & 3) * 4;
            float4 v = *(const float4*)&A[(size_t)(m0 + r) * K + k0 + c4];
            As[c4 + 0][r] = v.x; As[c4 + 1][r] = v.y;
            As[c4 + 2][r] = v.z; As[c4 + 3][r] = v.w;
        }
        #pragma unroll
        for (int i = 0; i < 2; i++) {
            int idx = tid + i * 256;
            int r = idx >> 5, c4 = (idx & 31) * 4;
            float4 v = make_float4(0.f, 0.f, 0.f, 0.f);
            if (n0 + c4 < N) v = *(const float4*)&B[(size_t)(k0 + r) * N + n0 + c4];
            *(float4*)&Bs[r][c4] = v;
        }
        __syncthreads();
        #pragma unroll
        for (int k = 0; k < 16; k++) {
            float4 ra = *(float4*)&As[k][ty * 4];
            float4 rb0 = *(float4*)&Bs[k][tx * 8];
            float4 rb1 = *(float4*)&Bs[k][tx * 8 + 4];
            float rav[4] = {ra.x, ra.y, ra.z, ra.w};
            float rbv[8] = {rb0.x, rb0.y, rb0.z, rb0.w, rb1.x, rb1.y, rb1.z, rb1.w};
            #pragma unroll
            for (int i = 0; i < 4; i++)
                #pragma unroll
                for (int j = 0; j < 8; j++)
                    acc[i][j] = fmaf(rav[i], rbv[j], acc[i][j]);
        }
        __syncthreads();
    }
    const int c = n0 + tx * 8;
    if (c < N) {
        float4 b0 = *(const float4*)&bias[c];
        float4 b1 = *(const float4*)&bias[c + 4];
        #pragma unroll
        for (int i = 0; i < 4; i++) {
            int r = m0 + ty * 4 + i;
            float4 v0 = make_float4(acc[i][0] + b0.x, acc[i][1] + b0.y,
                                    acc[i][2] + b0.z, acc[i][3] + b0.w);
            float4 v1 = make_float4(acc[i][4] + b1.x, acc[i][5] + b1.y,
                                    acc[i][6] + b1.z, acc[i][7] + b1.w);
            *(float4*)&C[(size_t)r * N + c]     = v0;
            *(float4*)&C[(size_t)r * N + c + 4] = v1;
        }
    }
}

// ===========================================================================
// Combined kernel:
//   blocks [0, 2100): value projection (tf32 mma), BM=128 x BN=128,
//     256 threads, 2 CTAs/SM, cp.async double-buffered.
//   blocks [2100, 2325): q-projection SIMT tiles (4800 x 288, K=256)
// ===========================================================================
#define VST 36
#define VA_FLOATS (128 * VST)                      // 4608
#define VBUF_FLOATS (2 * VA_FLOATS)                // 9216
#define VSMEM_BYTES (2 * VBUF_FLOATS * 4)          // 73728
#define NVALBLK 2100

__global__ __launch_bounds__(256, 2) void fused_mma_kernel(
    const float* __restrict__ A,      // value (134400 x 256)
    const float* __restrict__ WT,     // W_val^T (256 x 256), pre-rounded
    const float* __restrict__ bias,   // b_val
    float* __restrict__ C,            // g_v
    const float* __restrict__ Aq,     // query (4800 x 256)
    const float* __restrict__ Bq,     // g_wq (256 x 288)
    const float* __restrict__ biasq,  // g_bq
    float* __restrict__ Cq)           // g_q
{
    extern __shared__ float smem[];
    const int bid = blockIdx.x;

    if (bid >= NVALBLK) {
        const int qb = bid - NVALBLK;          // 0..224
        const int m0 = (qb % 75) * 64;
        const int n0 = (qb / 75) * 128;
        simt_gemm_tile(smem, Aq, Bq, biasq, Cq, 288, 256, m0, n0);
        return;
    }

    const int tid  = threadIdx.x;
    const int lane = tid & 31;
    const int wid  = tid >> 5;
    const int wr   = wid & 3;
    const int wc   = wid >> 2;
    const int gq   = lane >> 2;
    const int tg   = lane & 3;
    const int m0 = (bid >> 1) * 128;
    const int n0 = (bid & 1) * 128;

    const uint32_t sbase = smem_u32(smem);

    float acc[2][8][4];
    #pragma unroll
    for (int mt = 0; mt < 2; mt++)
        #pragma unroll
        for (int nt = 0; nt < 8; nt++)
            #pragma unroll
            for (int r = 0; r < 4; r++) acc[mt][nt][r] = 0.f;

    #define PREFETCH_CHUNK(cc, buf) do {                                         \
        const int k0_ = (cc) * 32;                                               \
        const uint32_t sA = sbase + (buf) * VBUF_FLOATS * 4;                     \
        const uint32_t sB = sA + VA_FLOATS * 4;                                  \
        _Pragma("unroll")                                                        \
        for (int i = 0; i < 4; i++) {                                            \
            int idx = tid + i * 256;            /* 0..1023 */                    \
            int r = idx >> 3, c4 = idx & 7;                                      \
            cp16(sA + (r * VST + c4 * 4) * 4,                                    \
                 &A[(size_t)(m0 + r) * 256 + k0_ + c4 * 4]);                     \
            cp16(sB + (r * VST + c4 * 4) * 4,                                    \
                 &WT[(size_t)(n0 + r) * 256 + k0_ + c4 * 4]);                    \
        }                                                                        \
        cp_commit();                                                             \
    } while (0)

    PREFETCH_CHUNK(0, 0);

    for (int c = 0; c < 8; c++) {
        const int buf = c & 1;
        if (c < 7) { PREFETCH_CHUNK(c + 1, (c + 1) & 1); cp_wait1(); }
        else       { cp_wait0(); }
        __syncthreads();

        const float* As = smem + buf * VBUF_FLOATS;
        const float* Bs = As + VA_FLOATS;

        #pragma unroll
        for (int kk = 0; kk < 4; kk++) {
            const int kb = kk * 8;
            uint32_t af[2][4];
            #pragma unroll
            for (int mt = 0; mt < 2; mt++) {
                const float* ab = &As[(wr * 32 + mt * 16 + gq) * VST + kb + tg];
                af[mt][0] = __float_as_uint(ab[0]);
                af[mt][1] = __float_as_uint(ab[8 * VST]);
                af[mt][2] = __float_as_uint(ab[4]);
                af[mt][3] = __float_as_uint(ab[8 * VST + 4]);
            }
            uint32_t bf[8][2];
            #pragma unroll
            for (int nt = 0; nt < 8; nt++) {
                const float* bb = &Bs[(wc * 64 + nt * 8 + gq) * VST + kb + tg];
                bf[nt][0] = __float_as_uint(bb[0]);
                bf[nt][1] = __float_as_uint(bb[4]);
            }
            #pragma unroll
            for (int mt = 0; mt < 2; mt++)
                #pragma unroll
                for (int nt = 0; nt < 8; nt++)
                    mma_tf32_16x8x8(acc[mt][nt][0], acc[mt][nt][1],
                                    acc[mt][nt][2], acc[mt][nt][3],
                                    af[mt][0], af[mt][1], af[mt][2], af[mt][3],
                                    bf[nt][0], bf[nt][1]);
        }
        __syncthreads();
    }
    #undef PREFETCH_CHUNK

    #pragma unroll
    for (int mt = 0; mt < 2; mt++) {
        #pragma unroll
        for (int nt = 0; nt < 8; nt++) {
            const int col = n0 + wc * 64 + nt * 8 + tg * 2;
            const float bx = __ldg(&bias[col]), by = __ldg(&bias[col + 1]);
            const int r0 = m0 + wr * 32 + mt * 16 + gq;
            float2 v0 = make_float2(acc[mt][nt][0] + bx, acc[mt][nt][1] + by);
            float2 v1 = make_float2(acc[mt][nt][2] + bx, acc[mt][nt][3] + by);
            *(float2*)&C[(size_t)r0 * 256 + col]       = v0;
            *(float2*)&C[(size_t)(r0 + 8) * 256 + col] = v1;
        }
    }
}

// ===========================================================================
// Standalone small GEMM (out-projection): grid (N/128, M/64), 256 threads
// ===========================================================================
__global__ __launch_bounds__(256) void small_gemm_kernel(
    const float* __restrict__ A, const float* __restrict__ B,
    const float* __restrict__ bias, float* __restrict__ C, int N, int K)
{
    __shared__ float sm[16 * 68 + 16 * 132];
    simt_gemm_tile(sm, A, B, bias, C, N, K, blockIdx.y * 64, blockIdx.x * 128);
}

// ===========================================================================
// Fused softmax + location + bilinear sampling (g_q stride 288)
// ===========================================================================
__global__ __launch_bounds__(256) void msda_sample_kernel(
    const float* __restrict__ ref_points, float* __restrict__ out)
{
    const int b = blockIdx.x;
    const int n = b / LQ;
    const int tid = threadIdx.x;
    const int lane = tid & 31;
    const int h = tid >> 5;

    __shared__ float s_aw[96];
    __shared__ float s_gx[96];
    __shared__ float s_gy[96];

    {
        float logit = (lane < 12) ? g_q[(size_t)b * 288 + 192 + h * 12 + lane] : -INFINITY;
        float m = logit;
        #pragma unroll
        for (int o = 8; o; o >>= 1) m = fmaxf(m, __shfl_xor_sync(0xffffffffu, m, o, 16));
        float e = (lane < 12) ? expf(logit - m) : 0.f;
        float s = e;
        #pragma unroll
        for (int o = 8; o; o >>= 1) s += __shfl_xor_sync(0xffffffffu, s, o, 16);
        if (lane < 12) s_aw[h * 12 + lane] = e / s;
    }

    if (tid < 96) {
        const int h2 = tid / 12;
        const int rem = tid % 12;
        const int l = rem >> 2;
        const int p = rem & 3;
        const float* rp = &ref_points[((size_t)b * NLVL + l) * 4];
        const size_t obase = (size_t)b * 288 + ((size_t)(h2 * NLVL + l) * NPT + p) * 2;
        float ox = g_q[obase + 0];
        float oy = g_q[obase + 1];
        float lx = rp[0] + ox * 0.125f * rp[2];
        float ly = rp[1] + oy * 0.125f * rp[3];
        const int Wl = (l == 0) ? 80 : (l == 1) ? 40 : 20;
        s_gx[tid] = lx * (float)Wl - 0.5f;
        s_gy[tid] = ly * (float)Wl - 0.5f;
    }
    __syncthreads();

    float acc = 0.f;
    const float* vbase = g_v + (size_t)n * LV * CC + h * HD + lane;

    #pragma unroll
    for (int j = 0; j < 12; j++) {
        const int l = j >> 2;
        const int Wl = (l == 0) ? 80 : (l == 1) ? 40 : 20;
        const int st = (l == 0) ? 0 : (l == 1) ? 6400 : 8000;

        float gx = s_gx[h * 12 + j];
        float gy = s_gy[h * 12 + j];
        float aw = s_aw[h * 12 + j];

        float x0f = floorf(gx), y0f = floorf(gy);
        int x0 = (int)x0f, y0 = (int)y0f;
        float wx = gx - x0f, wy = gy - y0f;

        bool vx0 = (x0 >= 0) && (x0 < Wl);
        bool vx1 = (x0 + 1 >= 0) && (x0 + 1 < Wl);
        bool vy0 = (y0 >= 0) && (y0 < Wl);
        bool vy1 = (y0 + 1 >= 0) && (y0 + 1 < Wl);

        const float* p00 = vbase + ((ptrdiff_t)st + (ptrdiff_t)y0 * Wl + x0) * CC;
        float v00 = (vx0 && vy0) ? p00[0] : 0.f;
        float v01 = (vx1 && vy0) ? p00[CC] : 0.f;
        float v10 = (vx0 && vy1) ? p00[(ptrdiff_t)Wl * CC] : 0.f;
        float v11 = (vx1 && vy1) ? p00[(ptrdiff_t)(Wl + 1) * CC] : 0.f;

        float top = v00 + wx * (v01 - v00);
        float bot = v10 + wx * (v11 - v10);
        acc = fmaf(aw, top + wy * (bot - top), acc);
    }

    out[(size_t)b * CC + h * HD + lane] = acc;
}

// ===========================================================================
// Launch
// ===========================================================================
extern "C" void kernel_launch(void* const* d_in, const int* in_sizes, int n_in,
                              void* d_out, int out_size)
{
    const float* query  = (const float*)d_in[0];
    const float* refp   = (const float*)d_in[1];
    const float* value  = (const float*)d_in[2];
    const float* W_off  = (const float*)d_in[3];
    const float* b_off  = (const float*)d_in[4];
    const float* W_attn = (const float*)d_in[5];
    const float* b_attn = (const float*)d_in[6];
    const float* W_val  = (const float*)d_in[7];
    const float* b_val  = (const float*)d_in[8];
    const float* W_out  = (const float*)d_in[9];
    const float* b_out  = (const float*)d_in[10];
    float* out = (float*)d_out;

    static float *gv = nullptr, *gwt, *gwq, *gbq, *gq, *gsamp;
    if (!gv) {
        cudaGetSymbolAddress((void**)&gv,    g_v);
        cudaGetSymbolAddress((void**)&gwt,   g_wt);
        cudaGetSymbolAddress((void**)&gwq,   g_wq);
        cudaGetSymbolAddress((void**)&gbq,   g_bq);
        cudaGetSymbolAddress((void**)&gq,    g_q);
        cudaGetSymbolAddress((void**)&gsamp, g_samp);
        cudaFuncSetAttribute(fused_mma_kernel,
                             cudaFuncAttributeMaxDynamicSharedMemorySize, VSMEM_BYTES);
    }

    const int MQ = NB * LQ;       // 4800

    // 0) prep: W_val^T (tf32-rounded) + [W_off|W_attn] concat
    transpose256_kernel<<<dim3(8, 8), dim3(32, 8)>>>(W_val, gwt);
    prep_qcat_kernel<<<288, 256>>>(W_off, b_off, W_attn, b_attn, gwq, gbq);

    // 1) fused: value projection (2100 mma blocks) + q projection (225 SIMT blocks)
    fused_mma_kernel<<<NVALBLK + 225, 256, VSMEM_BYTES>>>(
        value, gwt, b_val, gv, query, gwq, gbq, gq);

    // 2) softmax + locations + bilinear sampling
    msda_sample_kernel<<<MQ, 256>>>(refp, gsamp);

    // 3) output projection (N=256: 2 x 75 tiles)
    small_gemm_kernel<<<dim3(2, MQ / 64), 256>>>(gsamp, W_out, b_out, out, 256, 256);
}